// round 11
// baseline (speedup 1.0000x reference)
#include <cuda_runtime.h>
#include <cstdint>

#define NB  32
#define NC  192
#define NL  4096
#define CPB 2                  // channels per gather block
#define NCB (NC / CPB)         // 96 channel-groups per batch
#define GBLK (NB * NCB)        // 3072 gather blocks
#define GT  512                // gather threads per block

// Scratch for the scalar kernel only (no dynamic allocation allowed)
__device__ int   g_cnt[NB];
__device__ float g_th[NB];
__device__ int   g_ticket;     // zero-initialized; reset by last block each run

__device__ __forceinline__ void pdl_trigger() {
    asm volatile("griddepcontrol.launch_dependents;" ::: "memory");
}

// ---------------------------------------------------------------------------
// Scalar kernel (PDL primary): per-batch theta & keep-count, cross-batch
// reduction by the last-arriving block. Depends only on delta, so it runs
// fully concurrent with the gather grid. 32 blocks x 256 threads.
// ---------------------------------------------------------------------------
__global__ __launch_bounds__(256) void scalars_kernel(const float* __restrict__ delta,
                                                      float* __restrict__ out_kr,
                                                      float* __restrict__ out_tm)
{
    pdl_trigger();   // all 32 blocks are wave-1: gather grid launches immediately

    const int b    = blockIdx.x;
    const int tid  = threadIdx.x;
    const int lane = tid & 31;
    const int warp = tid >> 5;   // 8 warps

    __shared__ float  smn[8], smx[8];
    __shared__ double ssum[8], ssq[8];
    __shared__ int    scnt[8];
    __shared__ float  s_lo, s_rng, s_theta;

    const float4* dp = reinterpret_cast<const float4*>(delta + (size_t)b * NL) + tid * 4;
    float a[16];
    #pragma unroll
    for (int i = 0; i < 4; i++) {
        float4 v = dp[i];
        a[4*i+0] = fabsf(v.x); a[4*i+1] = fabsf(v.y);
        a[4*i+2] = fabsf(v.z); a[4*i+3] = fabsf(v.w);
    }

    float mn = a[0], mx = a[0];
    double s0 = 0.0, s1 = 0.0, q0 = 0.0, q1 = 0.0;
    #pragma unroll
    for (int i = 0; i < 8; i++) {
        mn = fminf(mn, fminf(a[2*i], a[2*i+1]));
        mx = fmaxf(mx, fmaxf(a[2*i], a[2*i+1]));
        double d0 = (double)a[2*i], d1 = (double)a[2*i+1];
        s0 += d0; q0 += d0 * d0;
        s1 += d1; q1 += d1 * d1;
    }
    double s = s0 + s1, q = q0 + q1;

    #pragma unroll
    for (int o = 16; o; o >>= 1) {
        mn = fminf(mn, __shfl_xor_sync(0xffffffffu, mn, o));
        mx = fmaxf(mx, __shfl_xor_sync(0xffffffffu, mx, o));
        s += __shfl_xor_sync(0xffffffffu, s, o);
        q += __shfl_xor_sync(0xffffffffu, q, o);
    }
    if (lane == 0) { smn[warp] = mn; smx[warp] = mx; ssum[warp] = s; ssq[warp] = q; }
    __syncthreads();

    if (warp == 0) {
        mn = (lane < 8) ? smn[lane] :  1e30f;
        mx = (lane < 8) ? smx[lane] : -1e30f;
        s  = (lane < 8) ? ssum[lane] : 0.0;
        q  = (lane < 8) ? ssq[lane]  : 0.0;
        #pragma unroll
        for (int o = 4; o; o >>= 1) {
            mn = fminf(mn, __shfl_xor_sync(0xffffffffu, mn, o));
            mx = fmaxf(mx, __shfl_xor_sync(0xffffffffu, mx, o));
            s += __shfl_xor_sync(0xffffffffu, s, o);
            q += __shfl_xor_sync(0xffffffffu, q, o);
        }
        if (lane == 0) {
            float lo  = mn;
            float rng = fmaxf(mx - lo, 1e-3f);
            double mu_a  = s / (double)NL;
            double var_a = (q - s * s / (double)NL) / (double)(NL - 1);
            if (var_a < 0.0) var_a = 0.0;
            s_lo = lo; s_rng = rng;
            s_theta = (float)((mu_a - (double)lo) / (double)rng - 0.1 * sqrt(var_a) / (double)rng);
        }
    }
    __syncthreads();

    const float lo = s_lo, rng = s_rng, theta = s_theta;
    int local = 0;
    #pragma unroll
    for (int i = 0; i < 16; i++) {
        float imp = (a[i] - lo) / rng;
        local += (imp >= theta) ? 1 : 0;
    }
    #pragma unroll
    for (int o = 16; o; o >>= 1) local += __shfl_xor_sync(0xffffffffu, local, o);
    if (lane == 0) scnt[warp] = local;
    __syncthreads();

    if (tid == 0) {
        int cnt = 0;
        #pragma unroll
        for (int i = 0; i < 8; i++) cnt += scnt[i];
        g_cnt[b] = cnt;
        g_th[b]  = theta;
        __threadfence();
        int t = atomicAdd(&g_ticket, 1);
        if (t == NB - 1) {
            __threadfence();
            float cs = 0.f, ts = 0.f;
            for (int i = 0; i < NB; i++) { cs += (float)g_cnt[i]; ts += g_th[i]; }
            *out_kr = (cs / (float)NB) / (float)NL;
            *out_tm = ts / (float)NB;
            g_ticket = 0;   // reset for the next graph replay
        }
    }
}

// ---------------------------------------------------------------------------
// Fused gather kernel: each block recomputes its batch's stats + compaction
// order in SMEM (deterministic, bit-identical across blocks of a batch),
// with its x staging LDGs already in flight to hide the recompute latency.
// 3072 blocks x 512 threads; smem = 32KB x-tile + 16KB order.
// ---------------------------------------------------------------------------
__global__ __launch_bounds__(GT) void gather_fused(const float* __restrict__ x,
                                                   const float* __restrict__ delta,
                                                   float* __restrict__ y)
{
    __shared__ float  sx[CPB * NL];     // 32 KB
    __shared__ int    sord[NL];         // 16 KB
    __shared__ float  smn[16], smx[16];
    __shared__ double ssum[16], ssq[16];
    __shared__ int    wsum[16];
    __shared__ float  s_lo, s_rng, s_theta;

    const int blk  = blockIdx.x;
    const int tid  = threadIdx.x;
    const int lane = tid & 31;
    const int warp = tid >> 5;   // 16 warps
    const int b    = blk / NCB;
    const int c0   = (blk % NCB) * CPB;
    const size_t base = ((size_t)b * NC + c0) * NL;

    // A: x preload into registers — LDGs in flight during the stats recompute
    const float4* xp = reinterpret_cast<const float4*>(x + base);
    float4 xr[4];
    #pragma unroll
    for (int i = 0; i < 4; i++) xr[i] = __ldcs(&xp[tid + GT * i]);

    // B: stats recompute (8 delta elems per thread, contiguous tokens 8*tid..)
    const float4* dp = reinterpret_cast<const float4*>(delta + (size_t)b * NL) + tid * 2;
    float4 d0 = dp[0], d1 = dp[1];
    float a[8] = { fabsf(d0.x), fabsf(d0.y), fabsf(d0.z), fabsf(d0.w),
                   fabsf(d1.x), fabsf(d1.y), fabsf(d1.z), fabsf(d1.w) };

    float mn = a[0], mx = a[0];
    double s0 = 0.0, s1 = 0.0, q0 = 0.0, q1 = 0.0;
    #pragma unroll
    for (int i = 0; i < 4; i++) {
        mn = fminf(mn, fminf(a[2*i], a[2*i+1]));
        mx = fmaxf(mx, fmaxf(a[2*i], a[2*i+1]));
        double e0 = (double)a[2*i], e1 = (double)a[2*i+1];
        s0 += e0; q0 += e0 * e0;
        s1 += e1; q1 += e1 * e1;
    }
    double s = s0 + s1, q = q0 + q1;

    #pragma unroll
    for (int o = 16; o; o >>= 1) {
        mn = fminf(mn, __shfl_xor_sync(0xffffffffu, mn, o));
        mx = fmaxf(mx, __shfl_xor_sync(0xffffffffu, mx, o));
        s += __shfl_xor_sync(0xffffffffu, s, o);
        q += __shfl_xor_sync(0xffffffffu, q, o);
    }
    if (lane == 0) { smn[warp] = mn; smx[warp] = mx; ssum[warp] = s; ssq[warp] = q; }
    __syncthreads();                                   // S1

    if (warp == 0) {
        mn = (lane < 16) ? smn[lane] :  1e30f;
        mx = (lane < 16) ? smx[lane] : -1e30f;
        s  = (lane < 16) ? ssum[lane] : 0.0;
        q  = (lane < 16) ? ssq[lane]  : 0.0;
        #pragma unroll
        for (int o = 8; o; o >>= 1) {
            mn = fminf(mn, __shfl_xor_sync(0xffffffffu, mn, o));
            mx = fmaxf(mx, __shfl_xor_sync(0xffffffffu, mx, o));
            s += __shfl_xor_sync(0xffffffffu, s, o);
            q += __shfl_xor_sync(0xffffffffu, q, o);
        }
        if (lane == 0) {
            float lo  = mn;
            float rng = fmaxf(mx - lo, 1e-3f);
            double mu_a  = s / (double)NL;
            double var_a = (q - s * s / (double)NL) / (double)(NL - 1);
            if (var_a < 0.0) var_a = 0.0;
            s_lo = lo; s_rng = rng;
            s_theta = (float)((mu_a - (double)lo) / (double)rng - 0.1 * sqrt(var_a) / (double)rng);
        }
    }
    __syncthreads();                                   // S2

    // C: keep bits + stable block prefix scan -> compaction order in SMEM
    const float lo = s_lo, rng = s_rng, theta = s_theta;
    unsigned kbits = 0;
    int local = 0;
    #pragma unroll
    for (int i = 0; i < 8; i++) {
        float imp = (a[i] - lo) / rng;
        if (imp >= theta) { kbits |= (1u << i); local++; }
    }

    int incl = local;
    #pragma unroll
    for (int o = 1; o < 32; o <<= 1) {
        int t = __shfl_up_sync(0xffffffffu, incl, o);
        if (lane >= o) incl += t;
    }
    if (lane == 31) wsum[warp] = incl;
    __syncthreads();                                   // S3

    if (warp == 0) {
        int t = (lane < 16) ? wsum[lane] : 0;
        #pragma unroll
        for (int o = 1; o < 16; o <<= 1) {
            int u = __shfl_up_sync(0xffffffffu, t, o);
            if (lane >= o) t += u;
        }
        if (lane < 16) wsum[lane] = t;    // inclusive scan of warp totals
    }
    __syncthreads();                                   // S4

    const int cnt = wsum[15];
    int pos = (warp ? wsum[warp - 1] : 0) + (incl - local);
    const int l = tid * 8;
    #pragma unroll
    for (int i = 0; i < 8; i++) {
        if (kbits & (1u << i)) sord[pos++] = l + i;
    }
    for (int j = cnt + tid; j < NL; j += GT) sord[j] = 0;   // benign tail

    // D: commit staged x to SMEM
    #pragma unroll
    for (int i = 0; i < 4; i++) reinterpret_cast<float4*>(sx)[tid + GT * i] = xr[i];
    __syncthreads();                                   // S5

    // E: gather from SMEM, coalesced streaming stores
    const int4 o0 = reinterpret_cast<const int4*>(sord)[2 * tid];
    const int4 o1 = reinterpret_cast<const int4*>(sord)[2 * tid + 1];
    const int j0 = 8 * tid;

    #pragma unroll
    for (int r = 0; r < CPB; r++) {
        const float* sr = sx + r * NL;
        float4 r0, r1;
        r0.x = (j0     < cnt) ? sr[o0.x] : 0.0f;
        r0.y = (j0 + 1 < cnt) ? sr[o0.y] : 0.0f;
        r0.z = (j0 + 2 < cnt) ? sr[o0.z] : 0.0f;
        r0.w = (j0 + 3 < cnt) ? sr[o0.w] : 0.0f;
        r1.x = (j0 + 4 < cnt) ? sr[o1.x] : 0.0f;
        r1.y = (j0 + 5 < cnt) ? sr[o1.y] : 0.0f;
        r1.z = (j0 + 6 < cnt) ? sr[o1.z] : 0.0f;
        r1.w = (j0 + 7 < cnt) ? sr[o1.w] : 0.0f;
        float4* yp = reinterpret_cast<float4*>(y + base + (size_t)r * NL) + 2 * tid;
        __stcs(yp,     r0);
        __stcs(yp + 1, r1);
    }
}

extern "C" void kernel_launch(void* const* d_in, const int* in_sizes, int n_in,
                              void* d_out, int out_size)
{
    const float* x     = (const float*)d_in[0];   // [32,192,64,64]
    const float* delta = (const float*)d_in[1];   // [32,1,64,64]
    float* out = (float*)d_out;

    // Primary: tiny scalar kernel; fires launch_dependents at entry.
    scalars_kernel<<<NB, 256>>>(delta, out + (out_size - 2), out + (out_size - 1));

    // Secondary (PDL): the gather grid starts immediately and runs concurrently
    // with the scalar kernel — it has no data dependency on it.
    cudaLaunchConfig_t cfg = {};
    cfg.gridDim  = dim3(GBLK, 1, 1);
    cfg.blockDim = dim3(GT, 1, 1);
    cfg.dynamicSmemBytes = 0;
    cfg.stream = 0;
    cudaLaunchAttribute attr[1];
    attr[0].id = cudaLaunchAttributeProgrammaticStreamSerialization;
    attr[0].val.programmaticStreamSerializationAllowed = 1;
    cfg.attrs = attr;
    cfg.numAttrs = 1;
    cudaLaunchKernelEx(&cfg, gather_fused, x, delta, out);
}

// round 14
// speedup vs baseline: 2.9666x; 2.9666x over previous
#include <cuda_runtime.h>
#include <cstdint>

#define NB  32
#define NC  192
#define NL  4096
#define CPB 4                  // channels per gather block
#define NCB (NC / CPB)         // 48 channel-groups per batch
#define GBLK (NB * NCB)        // 1536 gather blocks
#define GT  512                // gather threads per block
#define GSMEM (CPB * NL * 4)   // 64 KB dynamic smem

// Scratch (no dynamic allocation allowed)
__device__ int   g_order[NB * NL];   // entries < count are rewritten each run;
                                     // all values are always valid ids 0..NL-1
__device__ int   g_count[NB];
__device__ float g_theta[NB];

__device__ __forceinline__ void pdl_trigger() {
    asm volatile("griddepcontrol.launch_dependents;" ::: "memory");
}
__device__ __forceinline__ void pdl_wait() {
    asm volatile("griddepcontrol.wait;" ::: "memory");
}

// ---------------------------------------------------------------------------
// Kernel 1: per-batch single-pass stats + stable compaction index build.
// 32 blocks x 1024 threads, 4 contiguous elements per thread. No tail fill.
// ---------------------------------------------------------------------------
__global__ __launch_bounds__(1024) void stats_scan_kernel(const float* __restrict__ delta)
{
    pdl_trigger();   // gather grid starts staging x immediately

    const int b    = blockIdx.x;
    const int tid  = threadIdx.x;
    const int lane = tid & 31;
    const int warp = tid >> 5;   // 32 warps

    __shared__ float  smn[32], smx[32];
    __shared__ double ssum[32], ssq[32];
    __shared__ int    wsum[32];
    __shared__ float  s_lo, s_rng, s_theta;

    float4 v = reinterpret_cast<const float4*>(delta + (size_t)b * NL)[tid];
    float a0 = fabsf(v.x), a1 = fabsf(v.y), a2 = fabsf(v.z), a3 = fabsf(v.w);

    float mn = fminf(fminf(a0, a1), fminf(a2, a3));
    float mx = fmaxf(fmaxf(a0, a1), fmaxf(a2, a3));
    double s = (double)a0 + (double)a1 + (double)a2 + (double)a3;
    double q = (double)a0 * a0 + (double)a1 * a1 + (double)a2 * a2 + (double)a3 * a3;

    #pragma unroll
    for (int o = 16; o; o >>= 1) {
        mn = fminf(mn, __shfl_xor_sync(0xffffffffu, mn, o));
        mx = fmaxf(mx, __shfl_xor_sync(0xffffffffu, mx, o));
        s += __shfl_xor_sync(0xffffffffu, s, o);
        q += __shfl_xor_sync(0xffffffffu, q, o);
    }
    if (lane == 0) { smn[warp] = mn; smx[warp] = mx; ssum[warp] = s; ssq[warp] = q; }
    __syncthreads();

    if (warp == 0) {
        mn = smn[lane]; mx = smx[lane]; s = ssum[lane]; q = ssq[lane];
        #pragma unroll
        for (int o = 16; o; o >>= 1) {
            mn = fminf(mn, __shfl_xor_sync(0xffffffffu, mn, o));
            mx = fmaxf(mx, __shfl_xor_sync(0xffffffffu, mx, o));
            s += __shfl_xor_sync(0xffffffffu, s, o);
            q += __shfl_xor_sync(0xffffffffu, q, o);
        }
        if (lane == 0) {
            float lo  = mn;
            float rng = fmaxf(mx - lo, 1e-3f);
            double mu_a  = s / (double)NL;
            double var_a = (q - s * s / (double)NL) / (double)(NL - 1);
            if (var_a < 0.0) var_a = 0.0;
            s_lo = lo; s_rng = rng;
            s_theta = (float)((mu_a - (double)lo) / (double)rng
                              - 0.1 * sqrt(var_a) / (double)rng);
        }
    }
    __syncthreads();

    const float lo = s_lo, rng = s_rng, theta = s_theta;

    // keep flags (per-element fp32 imp exactly as reference)
    float i0 = (a0 - lo) / rng, i1 = (a1 - lo) / rng;
    float i2 = (a2 - lo) / rng, i3 = (a3 - lo) / rng;
    int k0 = (i0 >= theta), k1 = (i1 >= theta), k2 = (i2 >= theta), k3 = (i3 >= theta);
    int local = k0 + k1 + k2 + k3;

    int incl = local;
    #pragma unroll
    for (int o = 1; o < 32; o <<= 1) {
        int t = __shfl_up_sync(0xffffffffu, incl, o);
        if (lane >= o) incl += t;
    }
    if (lane == 31) wsum[warp] = incl;
    __syncthreads();
    if (warp == 0) {
        int t = wsum[lane];
        #pragma unroll
        for (int o = 1; o < 32; o <<= 1) {
            int u = __shfl_up_sync(0xffffffffu, t, o);
            if (lane >= o) t += u;
        }
        wsum[lane] = t;
    }
    __syncthreads();

    int pos  = (warp ? wsum[warp - 1] : 0) + (incl - local);
    int base = b * NL;
    int l    = tid * 4;
    if (k0) g_order[base + pos++] = l;
    if (k1) g_order[base + pos++] = l + 1;
    if (k2) g_order[base + pos++] = l + 2;
    if (k3) g_order[base + pos++] = l + 3;
    // No tail fill: stale g_order entries are always valid ids 0..NL-1
    // (zero on first touch, previous-run ids on replays); gather forces
    // positions j >= cnt to 0.0f regardless of the index read.

    if (tid == 0) {
        g_count[b] = wsum[31];
        g_theta[b] = theta;
    }
}

// ---------------------------------------------------------------------------
// Kernel 2: gather. One block per (b, 4 channels); 512 threads; 64 KB dynamic
// smem. Stages all 4 channels to SMEM BEFORE pdl_wait (deep pre-wait DRAM
// window hides the stats kernel), then gathers with order loaded once and
// reused 4x. Block 0 emits the scalar outputs.
// ---------------------------------------------------------------------------
__global__ __launch_bounds__(GT) void gather_kernel(const float* __restrict__ x,
                                                    float* __restrict__ y,
                                                    float* __restrict__ out_kr,
                                                    float* __restrict__ out_tm)
{
    extern __shared__ float sx[];                // CPB * NL floats = 64 KB

    const int blk = blockIdx.x;
    const int tid = threadIdx.x;
    const int b   = blk / NCB;
    const int c0  = (blk % NCB) * CPB;
    const size_t base = ((size_t)b * NC + c0) * NL;

    // Pre-wait staging: 4 channels = 4096 float4, 512 threads -> 8 each.
    // Independent of the stats kernel -> overlaps with it under PDL.
    const float4* xp = reinterpret_cast<const float4*>(x + base);
    #pragma unroll
    for (int i = 0; i < CPB * NL / 4 / GT; i++)
        reinterpret_cast<float4*>(sx)[tid + GT * i] = xp[tid + GT * i];

    // Wait for stats grid completion (g_* visibility), then fetch order once.
    pdl_wait();
    const int4* op = reinterpret_cast<const int4*>(g_order + b * NL);
    const int4 o0 = op[2 * tid];
    const int4 o1 = op[2 * tid + 1];
    const int  cnt = g_count[b];
    __syncthreads();

    const int j = 8 * tid;
    #pragma unroll
    for (int r = 0; r < CPB; r++) {
        const float* sr = sx + r * NL;
        float4 r0, r1;
        r0.x = (j     < cnt) ? sr[o0.x] : 0.0f;
        r0.y = (j + 1 < cnt) ? sr[o0.y] : 0.0f;
        r0.z = (j + 2 < cnt) ? sr[o0.z] : 0.0f;
        r0.w = (j + 3 < cnt) ? sr[o0.w] : 0.0f;
        r1.x = (j + 4 < cnt) ? sr[o1.x] : 0.0f;
        r1.y = (j + 5 < cnt) ? sr[o1.y] : 0.0f;
        r1.z = (j + 6 < cnt) ? sr[o1.z] : 0.0f;
        r1.w = (j + 7 < cnt) ? sr[o1.w] : 0.0f;
        float4* yp = reinterpret_cast<float4*>(y + base + (size_t)r * NL) + 2 * tid;
        yp[0] = r0;
        yp[1] = r1;
    }

    // scalar outputs (visible after pdl_wait)
    if (blk == 0 && tid < 32) {
        float cntf = (float)g_count[tid];
        float th   = g_theta[tid];
        #pragma unroll
        for (int o2 = 16; o2; o2 >>= 1) {
            cntf += __shfl_xor_sync(0xffffffffu, cntf, o2);
            th   += __shfl_xor_sync(0xffffffffu, th,   o2);
        }
        if (tid == 0) {
            *out_kr = (cntf / (float)NB) / (float)NL;
            *out_tm = th / (float)NB;
        }
    }
}

extern "C" void kernel_launch(void* const* d_in, const int* in_sizes, int n_in,
                              void* d_out, int out_size)
{
    const float* x     = (const float*)d_in[0];   // [32,192,64,64]
    const float* delta = (const float*)d_in[1];   // [32,1,64,64]
    float* out = (float*)d_out;

    // Unconditional every call (deterministic; no static guards allowed).
    cudaFuncSetAttribute(gather_kernel,
                         cudaFuncAttributeMaxDynamicSharedMemorySize, GSMEM);

    stats_scan_kernel<<<NB, 1024>>>(delta);

    cudaLaunchConfig_t cfg = {};
    cfg.gridDim  = dim3(GBLK, 1, 1);
    cfg.blockDim = dim3(GT, 1, 1);
    cfg.dynamicSmemBytes = GSMEM;
    cfg.stream = 0;
    cudaLaunchAttribute attr[1];
    attr[0].id = cudaLaunchAttributeProgrammaticStreamSerialization;
    attr[0].val.programmaticStreamSerializationAllowed = 1;
    cfg.attrs = attr;
    cfg.numAttrs = 1;
    cudaLaunchKernelEx(&cfg, gather_kernel, x, out,
                       out + (out_size - 2), out + (out_size - 1));
}